// round 1
// baseline (speedup 1.0000x reference)
#include <cuda_runtime.h>

#define NN_MAX 50000
#define ME_MAX 20000
#define E_MAX  800000

// ---------------- scratch (static device globals; no allocation) ----------------
__device__ float g_Q[NN_MAX * 128];
__device__ float g_K[ME_MAX * 128];
__device__ float g_V[ME_MAX * 128];
__device__ float g_attn[NN_MAX * 128];
__device__ int   g_count[NN_MAX];
__device__ int   g_offset[NN_MAX + 1];
__device__ int   g_cursor[NN_MAX];
__device__ int   g_edge_dst[E_MAX];

// ---------------- CSR build ----------------
__global__ void k_zero(int n) {
    int i = blockIdx.x * blockDim.x + threadIdx.x;
    if (i < n) g_count[i] = 0;
}

__global__ void k_hist(const int* __restrict__ src, int E) {
    int e = blockIdx.x * blockDim.x + threadIdx.x;
    if (e < E) atomicAdd(&g_count[src[e]], 1);
}

// single block, 1024 threads: exclusive scan of g_count[0..n) -> g_offset, g_cursor
__global__ void k_scan(int n) {
    __shared__ int sm[1024];
    int t = threadIdx.x;
    int chunk = (n + 1023) >> 10;
    int b = t * chunk;
    int e = min(b + chunk, n);
    int s = 0;
    for (int i = b; i < e; i++) s += g_count[i];
    sm[t] = s;
    __syncthreads();
    for (int o = 1; o < 1024; o <<= 1) {
        int v = (t >= o) ? sm[t - o] : 0;
        __syncthreads();
        sm[t] += v;
        __syncthreads();
    }
    int run = (t == 0) ? 0 : sm[t - 1];
    for (int i = b; i < e; i++) {
        int c = g_count[i];
        g_offset[i] = run;
        g_cursor[i] = run;
        run += c;
    }
    if (t == 1023) g_offset[n] = sm[1023];
}

__global__ void k_scatter(const int* __restrict__ src, const int* __restrict__ dst, int E) {
    int e = blockIdx.x * blockDim.x + threadIdx.x;
    if (e < E) {
        int p = atomicAdd(&g_cursor[src[e]], 1);
        g_edge_dst[p] = dst[e];
    }
}

// ---------------- tiled fp32 SGEMM: C[M,128] = A[M,128] @ W[128,128] + bias (+R) ----------------
template <bool RESID>
__global__ __launch_bounds__(256, 2) void k_gemm(
    const float* __restrict__ A, const float* __restrict__ W,
    const float* __restrict__ bias, const float* __restrict__ R,
    float* __restrict__ C, int M)
{
    __shared__ float As[16][128];
    __shared__ float Bs[16][128];
    int tid = threadIdx.x;
    int tx = tid & 15;   // output col group (8 cols)
    int ty = tid >> 4;   // output row group (8 rows)
    int row0 = blockIdx.x * 128;

    float c[8][8];
#pragma unroll
    for (int i = 0; i < 8; i++)
#pragma unroll
        for (int j = 0; j < 8; j++) c[i][j] = 0.0f;

    int am = tid >> 1;           // 0..127 row within tile
    int ak = (tid & 1) * 8;      // 0 or 8
    int arow = row0 + am;
    if (arow >= M) arow = M - 1; // clamp reads; stores are guarded
    const float* Ap = A + (size_t)arow * 128;
    int bkr = tid >> 4;          // 0..15
    int bn  = (tid & 15) * 8;

    for (int k0 = 0; k0 < 128; k0 += 16) {
        float4 a0 = *(const float4*)(Ap + k0 + ak);
        float4 a1 = *(const float4*)(Ap + k0 + ak + 4);
        As[ak + 0][am] = a0.x; As[ak + 1][am] = a0.y;
        As[ak + 2][am] = a0.z; As[ak + 3][am] = a0.w;
        As[ak + 4][am] = a1.x; As[ak + 5][am] = a1.y;
        As[ak + 6][am] = a1.z; As[ak + 7][am] = a1.w;
        *(float4*)&Bs[bkr][bn]     = *(const float4*)(W + (k0 + bkr) * 128 + bn);
        *(float4*)&Bs[bkr][bn + 4] = *(const float4*)(W + (k0 + bkr) * 128 + bn + 4);
        __syncthreads();
#pragma unroll
        for (int kk = 0; kk < 16; kk++) {
            float4 aA = *(float4*)&As[kk][ty * 8];
            float4 aB = *(float4*)&As[kk][ty * 8 + 4];
            float4 bA = *(float4*)&Bs[kk][tx * 8];
            float4 bB = *(float4*)&Bs[kk][tx * 8 + 4];
            float ar[8] = {aA.x, aA.y, aA.z, aA.w, aB.x, aB.y, aB.z, aB.w};
            float br[8] = {bA.x, bA.y, bA.z, bA.w, bB.x, bB.y, bB.z, bB.w};
#pragma unroll
            for (int i = 0; i < 8; i++)
#pragma unroll
                for (int j = 0; j < 8; j++)
                    c[i][j] += ar[i] * br[j];
        }
        __syncthreads();
    }

#pragma unroll
    for (int i = 0; i < 8; i++) {
        int m = row0 + ty * 8 + i;
        if (m < M) {
#pragma unroll
            for (int j = 0; j < 8; j += 4) {
                int n = tx * 8 + j;
                float4 o;
                o.x = c[i][j + 0] + bias[n + 0];
                o.y = c[i][j + 1] + bias[n + 1];
                o.z = c[i][j + 2] + bias[n + 2];
                o.w = c[i][j + 3] + bias[n + 3];
                if (RESID) {
                    float4 r = *(const float4*)(R + (size_t)m * 128 + n);
                    o.x += r.x; o.y += r.y; o.z += r.z; o.w += r.w;
                }
                *(float4*)(C + (size_t)m * 128 + n) = o;
            }
        }
    }
}

// ---------------- fused per-node attention (one warp per node) ----------------
// out_attn[n,:] = sum_e exp(s_e) * V[dst_e] / sum_e exp(s_e)  (per head)
// s_e = dot_head(Q[n], K[dst_e]) / sqrt(32). Max-subtraction skipped: s ~ N(0,1),
// global max ~5.5, exp safe in fp32; softmax is shift-invariant.
__global__ __launch_bounds__(256) void k_attn(int NN) {
    int warp = threadIdx.x >> 5;
    int lane = threadIdx.x & 31;
    int n = blockIdx.x * 8 + warp;
    if (n >= NN) return;

    const float4* Q4 = (const float4*)g_Q;
    const float4* K4 = (const float4*)g_K;
    const float4* V4 = (const float4*)g_V;

    float4 q = Q4[(size_t)n * 32 + lane];   // lane holds dims [lane*4, lane*4+4); head = lane/8
    float z = 0.0f;
    float ax = 0.0f, ay = 0.0f, az = 0.0f, aw = 0.0f;

    int beg = g_offset[n];
    int end = g_offset[n + 1];
    for (int j = beg; j < end; j++) {
        int d = g_edge_dst[j];                 // uniform across warp -> broadcast
        float4 k4 = K4[(size_t)d * 32 + lane];
        float4 v4 = V4[(size_t)d * 32 + lane];
        float p = q.x * k4.x + q.y * k4.y + q.z * k4.z + q.w * k4.w;
        // reduce over the 8 lanes of this head
        p += __shfl_xor_sync(0xffffffffu, p, 1);
        p += __shfl_xor_sync(0xffffffffu, p, 2);
        p += __shfl_xor_sync(0xffffffffu, p, 4);
        float e = __expf(p * 0.17677669529663687f);  // 1/sqrt(32)
        z += e;
        ax += e * v4.x; ay += e * v4.y; az += e * v4.z; aw += e * v4.w;
    }
    float inv = (z > 0.0f) ? (1.0f / z) : 0.0f;
    float4 o;
    o.x = ax * inv; o.y = ay * inv; o.z = az * inv; o.w = aw * inv;
    ((float4*)g_attn)[(size_t)n * 32 + lane] = o;
}

// ---------------- launch ----------------
extern "C" void kernel_launch(void* const* d_in, const int* in_sizes, int n_in,
                              void* d_out, int out_size)
{
    const float* x_node = (const float*)d_in[0];
    const float* x_edge = (const float*)d_in[1];
    const int*   src    = (const int*)d_in[2];
    const int*   dst    = (const int*)d_in[3];
    const float* Wq     = (const float*)d_in[4];
    const float* bq     = (const float*)d_in[5];
    const float* Wk     = (const float*)d_in[6];
    const float* bk     = (const float*)d_in[7];
    const float* Wv     = (const float*)d_in[8];
    const float* bv     = (const float*)d_in[9];
    const float* Wo     = (const float*)d_in[10];
    const float* bo     = (const float*)d_in[11];
    float* out = (float*)d_out;

    int NN = in_sizes[0] / 128;
    int ME = in_sizes[1] / 128;
    int E  = in_sizes[2];

    float *Qp, *Kp, *Vp, *Ap;
    cudaGetSymbolAddress((void**)&Qp, g_Q);
    cudaGetSymbolAddress((void**)&Kp, g_K);
    cudaGetSymbolAddress((void**)&Vp, g_V);
    cudaGetSymbolAddress((void**)&Ap, g_attn);

    k_zero<<<(NN + 255) / 256, 256>>>(NN);
    k_gemm<false><<<(NN + 127) / 128, 256>>>(x_node, Wq, bq, nullptr, Qp, NN);
    k_gemm<false><<<(ME + 127) / 128, 256>>>(x_edge, Wk, bk, nullptr, Kp, ME);
    k_gemm<false><<<(ME + 127) / 128, 256>>>(x_edge, Wv, bv, nullptr, Vp, ME);
    k_hist<<<(E + 255) / 256, 256>>>(src, E);
    k_scan<<<1, 1024>>>(NN);
    k_scatter<<<(E + 255) / 256, 256>>>(src, dst, E);
    k_attn<<<(NN + 7) / 8, 256>>>(NN);
    k_gemm<true><<<(NN + 127) / 128, 256>>>(Ap, Wo, bo, x_node, out, NN);
}

// round 4
// speedup vs baseline: 1.1030x; 1.1030x over previous
#include <cuda_runtime.h>
#include <cstdint>

#define NN_MAX 50000
#define ME_MAX 20000
#define E_MAX  800000

// ---------------- scratch (static device globals; no allocation) ----------------
__device__ float g_Q[NN_MAX * 128];
__device__ float g_K[ME_MAX * 128];
__device__ float g_V[ME_MAX * 128];
__device__ float g_attn[NN_MAX * 128];
__device__ int   g_count[NN_MAX];
__device__ int   g_offset[NN_MAX + 1];
__device__ int   g_cursor[NN_MAX];
__device__ int   g_edge_dst[E_MAX];

// ---------------- CSR build ----------------
__global__ void k_zero(int n) {
    int i = blockIdx.x * blockDim.x + threadIdx.x;
    if (i < n) g_count[i] = 0;
}

__global__ void k_hist(const int* __restrict__ src, int E) {
    int e = blockIdx.x * blockDim.x + threadIdx.x;
    if (e < E) atomicAdd(&g_count[src[e]], 1);
}

// single block, 1024 threads: exclusive scan of g_count[0..n) -> g_offset, g_cursor
__global__ void k_scan(int n) {
    __shared__ int sm[1024];
    int t = threadIdx.x;
    int chunk = (n + 1023) >> 10;
    int b = t * chunk;
    int e = min(b + chunk, n);
    int s = 0;
    for (int i = b; i < e; i++) s += g_count[i];
    sm[t] = s;
    __syncthreads();
    for (int o = 1; o < 1024; o <<= 1) {
        int v = (t >= o) ? sm[t - o] : 0;
        __syncthreads();
        sm[t] += v;
        __syncthreads();
    }
    int run = (t == 0) ? 0 : sm[t - 1];
    for (int i = b; i < e; i++) {
        int c = g_count[i];
        g_offset[i] = run;
        g_cursor[i] = run;
        run += c;
    }
    if (t == 1023) g_offset[n] = sm[1023];
}

__global__ void k_scatter(const int* __restrict__ src, const int* __restrict__ dst, int E) {
    int e = blockIdx.x * blockDim.x + threadIdx.x;
    if (e < E) {
        int p = atomicAdd(&g_cursor[src[e]], 1);
        g_edge_dst[p] = dst[e];
    }
}

// ---------------- 3xTF32 tensor-core GEMM ----------------
// C[M,128] = A[M,128] @ W[128,128] + bias (+R), fp32-accurate via hi/lo split:
//   a*b ~= ah*bh + ah*bl + al*bh  (missing al*bl ~ 2^-22 relative)
// Block: 128x128 tile, 512 threads = 16 warps (4m x 4n), warp tile 32x32.
// K staged in chunks of 16 through smem (A transposed to [k][m]).

// tf32 cvt: destination must be a b32 register; the bits are an fp32 pattern
// with the low mantissa truncated, so reinterpret to float for the residual.
__device__ __forceinline__ float f_tf32(float x) {
    uint32_t r;
    asm("cvt.rna.tf32.f32 %0, %1;" : "=r"(r) : "f"(x));
    return __uint_as_float(r);
}

__device__ __forceinline__ void mma_tf32(float* c, const uint32_t* a, const uint32_t* b) {
    asm volatile(
        "mma.sync.aligned.m16n8k8.row.col.f32.tf32.tf32.f32 "
        "{%0,%1,%2,%3}, {%4,%5,%6,%7}, {%8,%9}, {%0,%1,%2,%3};"
        : "+f"(c[0]), "+f"(c[1]), "+f"(c[2]), "+f"(c[3])
        : "r"(a[0]), "r"(a[1]), "r"(a[2]), "r"(a[3]), "r"(b[0]), "r"(b[1]));
}

#define SMS 136  // smem row stride (floats)

template <bool RESID>
__global__ __launch_bounds__(512) void k_gemm3(
    const float* __restrict__ A, const float* __restrict__ W,
    const float* __restrict__ bias, const float* __restrict__ R,
    float* __restrict__ C, int M)
{
    __shared__ float As_hi[16][SMS];
    __shared__ float As_lo[16][SMS];
    __shared__ float Ws_hi[16][SMS];
    __shared__ float Ws_lo[16][SMS];

    const int t = threadIdx.x;
    const int warp = t >> 5;
    const int lane = t & 31;
    const int l4 = lane & 3;
    const int l28 = lane >> 2;
    const int wm = warp & 3;   // warp row   (x32)
    const int wn = warp >> 2;  // warp col   (x32)
    const int row0 = blockIdx.x * 128;

    // staging coords
    const int sam = t >> 2;           // A row within tile  (0..127)
    const int saq = t & 3;            // A k-quad           (0..3) -> k = saq*4+c
    int arow = row0 + sam;
    if (arow >= M) arow = M - 1;      // clamp reads, guard stores
    const int swk = t >> 5;           // W k-row  (0..15)
    const int swn = (t & 31) * 4;     // W col    (0..124)

    float c[2][4][4];
#pragma unroll
    for (int mi = 0; mi < 2; mi++)
#pragma unroll
        for (int ni = 0; ni < 4; ni++)
#pragma unroll
            for (int r = 0; r < 4; r++) c[mi][ni][r] = 0.0f;

    for (int k0 = 0; k0 < 128; k0 += 16) {
        __syncthreads();
        // stage A (transposed -> [k][m]) with hi/lo split
        {
            float4 av = *(const float4*)(A + (size_t)arow * 128 + k0 + saq * 4);
            float v[4] = {av.x, av.y, av.z, av.w};
#pragma unroll
            for (int cc = 0; cc < 4; cc++) {
                float hi = f_tf32(v[cc]);
                As_hi[saq * 4 + cc][sam] = hi;
                As_lo[saq * 4 + cc][sam] = f_tf32(v[cc] - hi);
            }
        }
        // stage W ([k][n]) with hi/lo split
        {
            float4 wv = *(const float4*)(W + (size_t)(k0 + swk) * 128 + swn);
            float v[4] = {wv.x, wv.y, wv.z, wv.w};
            float4 hi4, lo4;
            float* hp = (float*)&hi4;
            float* lp = (float*)&lo4;
#pragma unroll
            for (int cc = 0; cc < 4; cc++) {
                hp[cc] = f_tf32(v[cc]);
                lp[cc] = f_tf32(v[cc] - hp[cc]);
            }
            *(float4*)&Ws_hi[swk][swn] = hi4;
            *(float4*)&Ws_lo[swk][swn] = lo4;
        }
        __syncthreads();

#pragma unroll
        for (int kk = 0; kk < 16; kk += 8) {
            uint32_t ah[2][4], al[2][4], bh[4][2], bl[4][2];
#pragma unroll
            for (int mi = 0; mi < 2; mi++) {
                int m0 = wm * 32 + mi * 16;
                ah[mi][0] = __float_as_uint(As_hi[kk + l4][m0 + l28]);
                ah[mi][1] = __float_as_uint(As_hi[kk + l4][m0 + l28 + 8]);
                ah[mi][2] = __float_as_uint(As_hi[kk + l4 + 4][m0 + l28]);
                ah[mi][3] = __float_as_uint(As_hi[kk + l4 + 4][m0 + l28 + 8]);
                al[mi][0] = __float_as_uint(As_lo[kk + l4][m0 + l28]);
                al[mi][1] = __float_as_uint(As_lo[kk + l4][m0 + l28 + 8]);
                al[mi][2] = __float_as_uint(As_lo[kk + l4 + 4][m0 + l28]);
                al[mi][3] = __float_as_uint(As_lo[kk + l4 + 4][m0 + l28 + 8]);
            }
#pragma unroll
            for (int ni = 0; ni < 4; ni++) {
                int n0 = wn * 32 + ni * 8;
                bh[ni][0] = __float_as_uint(Ws_hi[kk + l4][n0 + l28]);
                bh[ni][1] = __float_as_uint(Ws_hi[kk + l4 + 4][n0 + l28]);
                bl[ni][0] = __float_as_uint(Ws_lo[kk + l4][n0 + l28]);
                bl[ni][1] = __float_as_uint(Ws_lo[kk + l4 + 4][n0 + l28]);
            }
#pragma unroll
            for (int mi = 0; mi < 2; mi++)
#pragma unroll
                for (int ni = 0; ni < 4; ni++) {
                    mma_tf32(c[mi][ni], ah[mi], bh[ni]);
                    mma_tf32(c[mi][ni], ah[mi], bl[ni]);
                    mma_tf32(c[mi][ni], al[mi], bh[ni]);
                }
        }
    }

    // epilogue
#pragma unroll
    for (int mi = 0; mi < 2; mi++) {
#pragma unroll
        for (int ni = 0; ni < 4; ni++) {
            int gr = row0 + wm * 32 + mi * 16 + l28;
            int gc = wn * 32 + ni * 8 + 2 * l4;
            float b0 = bias[gc], b1 = bias[gc + 1];
            if (gr < M) {
                float2 o;
                o.x = c[mi][ni][0] + b0;
                o.y = c[mi][ni][1] + b1;
                if (RESID) {
                    float2 r = *(const float2*)(R + (size_t)gr * 128 + gc);
                    o.x += r.x; o.y += r.y;
                }
                *(float2*)(C + (size_t)gr * 128 + gc) = o;
            }
            if (gr + 8 < M) {
                float2 o;
                o.x = c[mi][ni][2] + b0;
                o.y = c[mi][ni][3] + b1;
                if (RESID) {
                    float2 r = *(const float2*)(R + (size_t)(gr + 8) * 128 + gc);
                    o.x += r.x; o.y += r.y;
                }
                *(float2*)(C + (size_t)(gr + 8) * 128 + gc) = o;
            }
        }
    }
}

// ---------------- fused per-node attention (one warp per node, 4-edge unroll) ----------------
__global__ __launch_bounds__(256) void k_attn(int NN) {
    int warp = threadIdx.x >> 5;
    int lane = threadIdx.x & 31;
    int n = blockIdx.x * 8 + warp;
    if (n >= NN) return;

    const float4* Q4 = (const float4*)g_Q;
    const float4* K4 = (const float4*)g_K;
    const float4* V4 = (const float4*)g_V;

    float4 q = Q4[(size_t)n * 32 + lane];   // lane holds dims [lane*4, lane*4+4); head = lane/8
    float z = 0.0f;
    float ax = 0.0f, ay = 0.0f, az = 0.0f, aw = 0.0f;
    const float sc = 0.17677669529663687f;  // 1/sqrt(32)

    int beg = g_offset[n];
    int end = g_offset[n + 1];
    int j = beg;
    for (; j + 4 <= end; j += 4) {
        int d0 = g_edge_dst[j + 0];
        int d1 = g_edge_dst[j + 1];
        int d2 = g_edge_dst[j + 2];
        int d3 = g_edge_dst[j + 3];
        float4 k0 = K4[(size_t)d0 * 32 + lane];
        float4 k1 = K4[(size_t)d1 * 32 + lane];
        float4 k2 = K4[(size_t)d2 * 32 + lane];
        float4 k3 = K4[(size_t)d3 * 32 + lane];
        float4 v0 = V4[(size_t)d0 * 32 + lane];
        float4 v1 = V4[(size_t)d1 * 32 + lane];
        float4 v2 = V4[(size_t)d2 * 32 + lane];
        float4 v3 = V4[(size_t)d3 * 32 + lane];

        float p0 = q.x * k0.x + q.y * k0.y + q.z * k0.z + q.w * k0.w;
        float p1 = q.x * k1.x + q.y * k1.y + q.z * k1.z + q.w * k1.w;
        float p2 = q.x * k2.x + q.y * k2.y + q.z * k2.z + q.w * k2.w;
        float p3 = q.x * k3.x + q.y * k3.y + q.z * k3.z + q.w * k3.w;
#pragma unroll
        for (int o = 1; o <= 4; o <<= 1) {
            p0 += __shfl_xor_sync(0xffffffffu, p0, o);
            p1 += __shfl_xor_sync(0xffffffffu, p1, o);
            p2 += __shfl_xor_sync(0xffffffffu, p2, o);
            p3 += __shfl_xor_sync(0xffffffffu, p3, o);
        }
        float e0 = __expf(p0 * sc);
        float e1 = __expf(p1 * sc);
        float e2 = __expf(p2 * sc);
        float e3 = __expf(p3 * sc);
        z += (e0 + e1) + (e2 + e3);
        ax += e0 * v0.x + e1 * v1.x + e2 * v2.x + e3 * v3.x;
        ay += e0 * v0.y + e1 * v1.y + e2 * v2.y + e3 * v3.y;
        az += e0 * v0.z + e1 * v1.z + e2 * v2.z + e3 * v3.z;
        aw += e0 * v0.w + e1 * v1.w + e2 * v2.w + e3 * v3.w;
    }
    for (; j < end; j++) {
        int d = g_edge_dst[j];
        float4 k4 = K4[(size_t)d * 32 + lane];
        float4 v4 = V4[(size_t)d * 32 + lane];
        float p = q.x * k4.x + q.y * k4.y + q.z * k4.z + q.w * k4.w;
        p += __shfl_xor_sync(0xffffffffu, p, 1);
        p += __shfl_xor_sync(0xffffffffu, p, 2);
        p += __shfl_xor_sync(0xffffffffu, p, 4);
        float e = __expf(p * sc);
        z += e;
        ax += e * v4.x; ay += e * v4.y; az += e * v4.z; aw += e * v4.w;
    }
    float inv = (z > 0.0f) ? (1.0f / z) : 0.0f;
    float4 o;
    o.x = ax * inv; o.y = ay * inv; o.z = az * inv; o.w = aw * inv;
    ((float4*)g_attn)[(size_t)n * 32 + lane] = o;
}

// ---------------- launch ----------------
extern "C" void kernel_launch(void* const* d_in, const int* in_sizes, int n_in,
                              void* d_out, int out_size)
{
    const float* x_node = (const float*)d_in[0];
    const float* x_edge = (const float*)d_in[1];
    const int*   src    = (const int*)d_in[2];
    const int*   dst    = (const int*)d_in[3];
    const float* Wq     = (const float*)d_in[4];
    const float* bq     = (const float*)d_in[5];
    const float* Wk     = (const float*)d_in[6];
    const float* bk     = (const float*)d_in[7];
    const float* Wv     = (const float*)d_in[8];
    const float* bv     = (const float*)d_in[9];
    const float* Wo     = (const float*)d_in[10];
    const float* bo     = (const float*)d_in[11];
    float* out = (float*)d_out;

    int NN = in_sizes[0] / 128;
    int ME = in_sizes[1] / 128;
    int E  = in_sizes[2];

    float *Qp, *Kp, *Vp, *Ap;
    cudaGetSymbolAddress((void**)&Qp, g_Q);
    cudaGetSymbolAddress((void**)&Kp, g_K);
    cudaGetSymbolAddress((void**)&Vp, g_V);
    cudaGetSymbolAddress((void**)&Ap, g_attn);

    k_zero<<<(NN + 255) / 256, 256>>>(NN);
    k_gemm3<false><<<(NN + 127) / 128, 512>>>(x_node, Wq, bq, nullptr, Qp, NN);
    k_gemm3<false><<<(ME + 127) / 128, 512>>>(x_edge, Wk, bk, nullptr, Kp, ME);
    k_gemm3<false><<<(ME + 127) / 128, 512>>>(x_edge, Wv, bv, nullptr, Vp, ME);
    k_hist<<<(E + 255) / 256, 256>>>(src, E);
    k_scan<<<1, 1024>>>(NN);
    k_scatter<<<(E + 255) / 256, 256>>>(src, dst, E);
    k_attn<<<(NN + 7) / 8, 256>>>(NN);
    k_gemm3<true><<<(NN + 127) / 128, 512>>>(Ap, Wo, bo, x_node, out, NN);
}

// round 7
// speedup vs baseline: 1.3595x; 1.2326x over previous
#include <cuda_runtime.h>
#include <cuda_bf16.h>
#include <cstdint>

#define NN_MAX 50000
#define ME_MAX 20000
#define E_MAX  800000

// ---------------- scratch (static device globals; no allocation) ----------------
__device__ float g_Q[NN_MAX * 128];
__device__ float g_K[ME_MAX * 128];
__device__ float g_V[ME_MAX * 128];
__device__ float g_attn[NN_MAX * 128];
__device__ int   g_count[NN_MAX];
__device__ int   g_offset[NN_MAX + 1];
__device__ int   g_cursor[NN_MAX];
__device__ int   g_edge_dst[E_MAX];
// split weights: [which][hi/lo][n*136 + k]  (bf16, transposed to [n][k], row stride 136)
__device__ __align__(16) __nv_bfloat16 g_Wsp[4][2][128 * 136];

// ---------------- CSR build ----------------
__global__ void k_zero(int n) {
    int i = blockIdx.x * blockDim.x + threadIdx.x;
    if (i < n) g_count[i] = 0;
}

__global__ void k_hist(const int* __restrict__ src, int E) {
    int e = blockIdx.x * blockDim.x + threadIdx.x;
    if (e < E) atomicAdd(&g_count[src[e]], 1);
}

__global__ void k_scan(int n) {
    __shared__ int sm[1024];
    int t = threadIdx.x;
    int chunk = (n + 1023) >> 10;
    int b = t * chunk;
    int e = min(b + chunk, n);
    int s = 0;
    for (int i = b; i < e; i++) s += g_count[i];
    sm[t] = s;
    __syncthreads();
    for (int o = 1; o < 1024; o <<= 1) {
        int v = (t >= o) ? sm[t - o] : 0;
        __syncthreads();
        sm[t] += v;
        __syncthreads();
    }
    int run = (t == 0) ? 0 : sm[t - 1];
    for (int i = b; i < e; i++) {
        int c = g_count[i];
        g_offset[i] = run;
        g_cursor[i] = run;
        run += c;
    }
    if (t == 1023) g_offset[n] = sm[1023];
}

__global__ void k_scatter(const int* __restrict__ src, const int* __restrict__ dst, int E) {
    int e = blockIdx.x * blockDim.x + threadIdx.x;
    if (e < E) {
        int p = atomicAdd(&g_cursor[src[e]], 1);
        g_edge_dst[p] = dst[e];
    }
}

// ---------------- weight split: W[k][n] fp32 -> bf16 hi/lo, transposed [n][k] ----------------
__global__ void k_splitW(const float* __restrict__ W0, const float* __restrict__ W1,
                         const float* __restrict__ W2, const float* __restrict__ W3) {
    int w = blockIdx.y;
    const float* W = (w == 0) ? W0 : (w == 1) ? W1 : (w == 2) ? W2 : W3;
    int gid = blockIdx.x * 256 + threadIdx.x;   // 0..16383
    int n = gid >> 7;
    int k = gid & 127;
    float x = W[k * 128 + n];
    __nv_bfloat16 h = __float2bfloat16_rn(x);
    __nv_bfloat16 l = __float2bfloat16_rn(x - __bfloat162float(h));
    g_Wsp[w][0][n * 136 + k] = h;
    g_Wsp[w][1][n * 136 + k] = l;
}

// ---------------- bf16 3-term tensor-core GEMM ----------------
// C[M,128] = A[M,128] @ W + bias (+R).  Per CTA: 64 rows x 128 cols, full K in smem,
// one barrier, then 8 unrolled k-steps of pure LDS+MMA.
// 256 thr = 8 warps (2m x 4n), warp tile 32x32, mma m16n8k16 bf16.

__device__ __forceinline__ void mma_bf16(float* c, const uint32_t* a, const uint32_t* b) {
    asm volatile(
        "mma.sync.aligned.m16n8k16.row.col.f32.bf16.bf16.f32 "
        "{%0,%1,%2,%3}, {%4,%5,%6,%7}, {%8,%9}, {%0,%1,%2,%3};"
        : "+f"(c[0]), "+f"(c[1]), "+f"(c[2]), "+f"(c[3])
        : "r"(a[0]), "r"(a[1]), "r"(a[2]), "r"(a[3]), "r"(b[0]), "r"(b[1]));
}

__device__ __forceinline__ void split2(float x, float y, uint32_t& h, uint32_t& l) {
    __nv_bfloat162 hb = __floats2bfloat162_rn(x, y);
    float hx = __bfloat162float(hb.x);
    float hy = __bfloat162float(hb.y);
    __nv_bfloat162 lb = __floats2bfloat162_rn(x - hx, y - hy);
    h = *(uint32_t*)&hb;
    l = *(uint32_t*)&lb;
}

#define WS 68  // row stride in b32 units (136 bf16)
#define GEMM_SMEM ((2 * 128 * WS + 2 * 64 * WS) * 4)  // 104448 bytes

template <bool RESID>
__global__ __launch_bounds__(256, 2) void k_gemmB(
    const float* __restrict__ A, const uint4* __restrict__ Wsp,
    const float* __restrict__ bias, const float* __restrict__ R,
    float* __restrict__ C, int M)
{
    extern __shared__ uint32_t sm[];
    uint32_t* sWh = sm;                      // 128*68
    uint32_t* sWl = sm + 128 * WS;           // 128*68
    uint32_t* sAh = sm + 2 * 128 * WS;       // 64*68
    uint32_t* sAl = sm + 2 * 128 * WS + 64 * WS;

    const int t = threadIdx.x;
    const int lane = t & 31, warp = t >> 5;
    const int l4 = lane & 3, l28 = lane >> 2;
    const int wm = warp & 1;    // x32 rows
    const int wn = warp >> 1;   // x32 cols
    const int row0 = blockIdx.x * 64;

    // stage W (hi+lo contiguous in global): 4352 uint4 -> 17/thread
    {
        uint4* dW = (uint4*)sWh;
#pragma unroll
        for (int i = 0; i < 17; i++)
            dW[t + i * 256] = Wsp[t + i * 256];
    }
    // stage A: 64 rows x 128 cols fp32, convert to bf16 hi/lo.  4 threads/row, 8 float4 each.
    {
        int m = t >> 2;
        int q = t & 3;
        int arow = row0 + m;
        if (arow >= M) arow = M - 1;
        const float4* Ap = (const float4*)(A + (size_t)arow * 128);
#pragma unroll
        for (int i = 0; i < 8; i++) {
            int col = q * 32 + i * 4;
            float4 v = Ap[col >> 2];
            uint32_t h01, l01, h23, l23;
            split2(v.x, v.y, h01, l01);
            split2(v.z, v.w, h23, l23);
            int o = m * WS + (col >> 1);
            sAh[o] = h01; sAh[o + 1] = h23;
            sAl[o] = l01; sAl[o + 1] = l23;
        }
    }
    __syncthreads();

    float c[2][4][4];
#pragma unroll
    for (int mi = 0; mi < 2; mi++)
#pragma unroll
        for (int ni = 0; ni < 4; ni++)
#pragma unroll
            for (int r = 0; r < 4; r++) c[mi][ni][r] = 0.0f;

#pragma unroll
    for (int kk = 0; kk < 8; kk++) {
        const int kb = kk * 8 + l4;   // b32 index into row (k = kk*16 + 2*l4)
        uint32_t ah[2][4], al[2][4], bh[4][2], bl[4][2];
#pragma unroll
        for (int mi = 0; mi < 2; mi++) {
            int r0 = (wm * 32 + mi * 16 + l28) * WS;
            int r1 = r0 + 8 * WS;
            ah[mi][0] = sAh[r0 + kb];     ah[mi][1] = sAh[r1 + kb];
            ah[mi][2] = sAh[r0 + kb + 4]; ah[mi][3] = sAh[r1 + kb + 4];
            al[mi][0] = sAl[r0 + kb];     al[mi][1] = sAl[r1 + kb];
            al[mi][2] = sAl[r0 + kb + 4]; al[mi][3] = sAl[r1 + kb + 4];
        }
#pragma unroll
        for (int ni = 0; ni < 4; ni++) {
            int n0 = (wn * 32 + ni * 8 + l28) * WS;
            bh[ni][0] = sWh[n0 + kb]; bh[ni][1] = sWh[n0 + kb + 4];
            bl[ni][0] = sWl[n0 + kb]; bl[ni][1] = sWl[n0 + kb + 4];
        }
#pragma unroll
        for (int mi = 0; mi < 2; mi++)
#pragma unroll
            for (int ni = 0; ni < 4; ni++) {
                mma_bf16(c[mi][ni], ah[mi], bh[ni]);
                mma_bf16(c[mi][ni], ah[mi], bl[ni]);
                mma_bf16(c[mi][ni], al[mi], bh[ni]);
            }
    }

    // epilogue: c0=(r,2c), c1=(r,2c+1), c2=(r+8,2c), c3=(r+8,2c+1)
#pragma unroll
    for (int mi = 0; mi < 2; mi++) {
#pragma unroll
        for (int ni = 0; ni < 4; ni++) {
            int gr = row0 + wm * 32 + mi * 16 + l28;
            int gc = wn * 32 + ni * 8 + 2 * l4;
            float b0 = bias[gc], b1 = bias[gc + 1];
            if (gr < M) {
                float2 o;
                o.x = c[mi][ni][0] + b0;
                o.y = c[mi][ni][1] + b1;
                if (RESID) {
                    float2 r = *(const float2*)(R + (size_t)gr * 128 + gc);
                    o.x += r.x; o.y += r.y;
                }
                *(float2*)(C + (size_t)gr * 128 + gc) = o;
            }
            if (gr + 8 < M) {
                float2 o;
                o.x = c[mi][ni][2] + b0;
                o.y = c[mi][ni][3] + b1;
                if (RESID) {
                    float2 r = *(const float2*)(R + (size_t)(gr + 8) * 128 + gc);
                    o.x += r.x; o.y += r.y;
                }
                *(float2*)(C + (size_t)(gr + 8) * 128 + gc) = o;
            }
        }
    }
}

// ---------------- fused per-node attention (one warp per node, 4-edge unroll) ----------------
__global__ __launch_bounds__(256) void k_attn(int NN) {
    int warp = threadIdx.x >> 5;
    int lane = threadIdx.x & 31;
    int n = blockIdx.x * 8 + warp;
    if (n >= NN) return;

    const float4* Q4 = (const float4*)g_Q;
    const float4* K4 = (const float4*)g_K;
    const float4* V4 = (const float4*)g_V;

    float4 q = Q4[(size_t)n * 32 + lane];
    float z = 0.0f;
    float ax = 0.0f, ay = 0.0f, az = 0.0f, aw = 0.0f;
    const float sc = 0.17677669529663687f;  // 1/sqrt(32)

    int beg = g_offset[n];
    int end = g_offset[n + 1];
    int j = beg;
    for (; j + 4 <= end; j += 4) {
        int d0 = g_edge_dst[j + 0];
        int d1 = g_edge_dst[j + 1];
        int d2 = g_edge_dst[j + 2];
        int d3 = g_edge_dst[j + 3];
        float4 k0 = K4[(size_t)d0 * 32 + lane];
        float4 k1 = K4[(size_t)d1 * 32 + lane];
        float4 k2 = K4[(size_t)d2 * 32 + lane];
        float4 k3 = K4[(size_t)d3 * 32 + lane];
        float4 v0 = V4[(size_t)d0 * 32 + lane];
        float4 v1 = V4[(size_t)d1 * 32 + lane];
        float4 v2 = V4[(size_t)d2 * 32 + lane];
        float4 v3 = V4[(size_t)d3 * 32 + lane];

        float p0 = q.x * k0.x + q.y * k0.y + q.z * k0.z + q.w * k0.w;
        float p1 = q.x * k1.x + q.y * k1.y + q.z * k1.z + q.w * k1.w;
        float p2 = q.x * k2.x + q.y * k2.y + q.z * k2.z + q.w * k2.w;
        float p3 = q.x * k3.x + q.y * k3.y + q.z * k3.z + q.w * k3.w;
#pragma unroll
        for (int o = 1; o <= 4; o <<= 1) {
            p0 += __shfl_xor_sync(0xffffffffu, p0, o);
            p1 += __shfl_xor_sync(0xffffffffu, p1, o);
            p2 += __shfl_xor_sync(0xffffffffu, p2, o);
            p3 += __shfl_xor_sync(0xffffffffu, p3, o);
        }
        float e0 = __expf(p0 * sc);
        float e1 = __expf(p1 * sc);
        float e2 = __expf(p2 * sc);
        float e3 = __expf(p3 * sc);
        z += (e0 + e1) + (e2 + e3);
        ax += e0 * v0.x + e1 * v1.x + e2 * v2.x + e3 * v3.x;
        ay += e0 * v0.y + e1 * v1.y + e2 * v2.y + e3 * v3.y;
        az += e0 * v0.z + e1 * v1.z + e2 * v2.z + e3 * v3.z;
        aw += e0 * v0.w + e1 * v1.w + e2 * v2.w + e3 * v3.w;
    }
    for (; j < end; j++) {
        int d = g_edge_dst[j];
        float4 k4 = K4[(size_t)d * 32 + lane];
        float4 v4 = V4[(size_t)d * 32 + lane];
        float p = q.x * k4.x + q.y * k4.y + q.z * k4.z + q.w * k4.w;
        p += __shfl_xor_sync(0xffffffffu, p, 1);
        p += __shfl_xor_sync(0xffffffffu, p, 2);
        p += __shfl_xor_sync(0xffffffffu, p, 4);
        float e = __expf(p * sc);
        z += e;
        ax += e * v4.x; ay += e * v4.y; az += e * v4.z; aw += e * v4.w;
    }
    float inv = (z > 0.0f) ? (1.0f / z) : 0.0f;
    float4 o;
    o.x = ax * inv; o.y = ay * inv; o.z = az * inv; o.w = aw * inv;
    ((float4*)g_attn)[(size_t)n * 32 + lane] = o;
}

// ---------------- launch ----------------
extern "C" void kernel_launch(void* const* d_in, const int* in_sizes, int n_in,
                              void* d_out, int out_size)
{
    const float* x_node = (const float*)d_in[0];
    const float* x_edge = (const float*)d_in[1];
    const int*   src    = (const int*)d_in[2];
    const int*   dst    = (const int*)d_in[3];
    const float* Wq     = (const float*)d_in[4];
    const float* bq     = (const float*)d_in[5];
    const float* Wk     = (const float*)d_in[6];
    const float* bk     = (const float*)d_in[7];
    const float* Wv     = (const float*)d_in[8];
    const float* bv     = (const float*)d_in[9];
    const float* Wo     = (const float*)d_in[10];
    const float* bo     = (const float*)d_in[11];
    float* out = (float*)d_out;

    int NN = in_sizes[0] / 128;
    int ME = in_sizes[1] / 128;
    int E  = in_sizes[2];

    float *Qp, *Kp, *Vp, *Ap;
    uint4* Wspp;
    cudaGetSymbolAddress((void**)&Qp, g_Q);
    cudaGetSymbolAddress((void**)&Kp, g_K);
    cudaGetSymbolAddress((void**)&Vp, g_V);
    cudaGetSymbolAddress((void**)&Ap, g_attn);
    cudaGetSymbolAddress((void**)&Wspp, g_Wsp);
    const size_t wstride = (size_t)2 * 128 * 136 * sizeof(__nv_bfloat16) / sizeof(uint4);

    cudaFuncSetAttribute(k_gemmB<false>, cudaFuncAttributeMaxDynamicSharedMemorySize, GEMM_SMEM);
    cudaFuncSetAttribute(k_gemmB<true>,  cudaFuncAttributeMaxDynamicSharedMemorySize, GEMM_SMEM);

    k_zero<<<(NN + 255) / 256, 256>>>(NN);
    k_splitW<<<dim3(64, 4), 256>>>(Wq, Wk, Wv, Wo);
    k_gemmB<false><<<(NN + 63) / 64, 256, GEMM_SMEM>>>(x_node, Wspp + 0 * wstride, bq, nullptr, Qp, NN);
    k_gemmB<false><<<(ME + 63) / 64, 256, GEMM_SMEM>>>(x_edge, Wspp + 1 * wstride, bk, nullptr, Kp, ME);
    k_gemmB<false><<<(ME + 63) / 64, 256, GEMM_SMEM>>>(x_edge, Wspp + 2 * wstride, bv, nullptr, Vp, ME);
    k_hist<<<(E + 255) / 256, 256>>>(src, E);
    k_scan<<<1, 1024>>>(NN);
    k_scatter<<<(E + 255) / 256, 256>>>(src, dst, E);
    k_attn<<<(NN + 7) / 8, 256>>>(NN);
    k_gemmB<true><<<(NN + 63) / 64, 256, GEMM_SMEM>>>(Ap, Wspp + 3 * wstride, bo, x_node, out, NN);
}

// round 10
// speedup vs baseline: 1.3701x; 1.0078x over previous
#include <cuda_runtime.h>
#include <cuda_bf16.h>
#include <cstdint>

#define NN_MAX 50000
#define ME_MAX 20000
#define E_MAX  800000

// ---------------- scratch (static device globals; no allocation) ----------------
__device__ float g_Q[NN_MAX * 128];
__device__ float g_K[ME_MAX * 128];
__device__ float g_V[ME_MAX * 128];
__device__ float g_attn[NN_MAX * 128];
__device__ int   g_count[NN_MAX];
__device__ int   g_offset[NN_MAX + 1];
__device__ int   g_cursor[NN_MAX];
__device__ int   g_edge_dst[E_MAX];
// split weights: [which][hi/lo][n*136 + k]  (bf16, transposed to [n][k], row stride 136)
__device__ __align__(16) __nv_bfloat16 g_Wsp[4][2][128 * 136];

// ---------------- CSR build ----------------
__global__ void k_zero(int n) {
    int i = blockIdx.x * blockDim.x + threadIdx.x;
    if (i < n) g_count[i] = 0;
}

__global__ void k_hist(const int* __restrict__ src, int E) {
    int e = blockIdx.x * blockDim.x + threadIdx.x;
    if (e < E) atomicAdd(&g_count[src[e]], 1);
}

__global__ void k_scan(int n) {
    __shared__ int sm[1024];
    int t = threadIdx.x;
    int chunk = (n + 1023) >> 10;
    int b = t * chunk;
    int e = min(b + chunk, n);
    int s = 0;
    for (int i = b; i < e; i++) s += g_count[i];
    sm[t] = s;
    __syncthreads();
    for (int o = 1; o < 1024; o <<= 1) {
        int v = (t >= o) ? sm[t - o] : 0;
        __syncthreads();
        sm[t] += v;
        __syncthreads();
    }
    int run = (t == 0) ? 0 : sm[t - 1];
    for (int i = b; i < e; i++) {
        int c = g_count[i];
        g_offset[i] = run;
        g_cursor[i] = run;
        run += c;
    }
    if (t == 1023) g_offset[n] = sm[1023];
}

__global__ void k_scatter(const int* __restrict__ src, const int* __restrict__ dst, int E) {
    int e = blockIdx.x * blockDim.x + threadIdx.x;
    if (e < E) {
        int p = atomicAdd(&g_cursor[src[e]], 1);
        g_edge_dst[p] = dst[e];
    }
}

// ---------------- weight split: W[k][n] fp32 -> bf16 hi/lo, transposed [n][k] ----------------
__global__ void k_splitW(const float* __restrict__ W0, const float* __restrict__ W1,
                         const float* __restrict__ W2, const float* __restrict__ W3) {
    int w = blockIdx.y;
    const float* W = (w == 0) ? W0 : (w == 1) ? W1 : (w == 2) ? W2 : W3;
    int gid = blockIdx.x * 256 + threadIdx.x;   // 0..16383
    int n = gid >> 7;
    int k = gid & 127;
    float x = W[k * 128 + n];
    __nv_bfloat16 h = __float2bfloat16_rn(x);
    __nv_bfloat16 l = __float2bfloat16_rn(x - __bfloat162float(h));
    g_Wsp[w][0][n * 136 + k] = h;
    g_Wsp[w][1][n * 136 + k] = l;
}

// ---------------- bf16 3-term tensor-core GEMM ----------------
// C[M,128] = A[M,128] @ W + bias (+R).  Per CTA: 64 rows x 128 cols, full K in smem,
// one barrier, then 8 unrolled k-steps; fragments via ldmatrix.x4 (64 LDSM/warp).
// 256 thr = 8 warps (2m x 4n), warp tile 32x32, mma m16n8k16 bf16.

__device__ __forceinline__ void mma_bf16(float* c, const uint32_t* a, const uint32_t* b) {
    asm volatile(
        "mma.sync.aligned.m16n8k16.row.col.f32.bf16.bf16.f32 "
        "{%0,%1,%2,%3}, {%4,%5,%6,%7}, {%8,%9}, {%0,%1,%2,%3};"
        : "+f"(c[0]), "+f"(c[1]), "+f"(c[2]), "+f"(c[3])
        : "r"(a[0]), "r"(a[1]), "r"(a[2]), "r"(a[3]), "r"(b[0]), "r"(b[1]));
}

__device__ __forceinline__ void ldsm4(uint32_t& r0, uint32_t& r1, uint32_t& r2, uint32_t& r3,
                                      uint32_t addr) {
    asm volatile("ldmatrix.sync.aligned.m8n8.x4.shared.b16 {%0,%1,%2,%3}, [%4];"
                 : "=r"(r0), "=r"(r1), "=r"(r2), "=r"(r3) : "r"(addr));
}

__device__ __forceinline__ void split2(float x, float y, uint32_t& h, uint32_t& l) {
    __nv_bfloat162 hb = __floats2bfloat162_rn(x, y);
    float hx = __bfloat162float(hb.x);
    float hy = __bfloat162float(hb.y);
    __nv_bfloat162 lb = __floats2bfloat162_rn(x - hx, y - hy);
    h = *(uint32_t*)&hb;
    l = *(uint32_t*)&lb;
}

#define WS 68  // row stride in b32 units (136 bf16, 272 bytes)
#define GEMM_SMEM ((2 * 128 * WS + 2 * 64 * WS) * 4)  // 104448 bytes
#define ROWB (WS * 4)                                  // 272 bytes per row
#define LO_W (128 * WS * 4)                            // byte offset sWh -> sWl
#define LO_A (64 * WS * 4)                             // byte offset sAh -> sAl

template <bool RESID>
__global__ __launch_bounds__(256, 2) void k_gemmB(
    const float* __restrict__ A, const uint4* __restrict__ Wsp,
    const float* __restrict__ bias, const float* __restrict__ R,
    float* __restrict__ C, int M)
{
    extern __shared__ uint32_t sm[];
    uint32_t* sWh = sm;                      // 128*68
    uint32_t* sWl = sm + 128 * WS;           // 128*68
    uint32_t* sAh = sm + 2 * 128 * WS;       // 64*68
    uint32_t* sAl = sm + 2 * 128 * WS + 64 * WS;

    const int t = threadIdx.x;
    const int lane = t & 31, warp = t >> 5;
    const int l4 = lane & 3, l28 = lane >> 2;
    const int wm = warp & 1;    // x32 rows
    const int wn = warp >> 1;   // x32 cols
    const int row0 = blockIdx.x * 64;

    // stage W (hi+lo contiguous in global): 4352 uint4 -> 17/thread
    {
        uint4* dW = (uint4*)sWh;
#pragma unroll
        for (int i = 0; i < 17; i++)
            dW[t + i * 256] = Wsp[t + i * 256];
    }
    // stage A: 64 rows x 128 cols fp32, convert to bf16 hi/lo.  4 threads/row, 8 float4 each.
    {
        int m = t >> 2;
        int q = t & 3;
        int arow = row0 + m;
        if (arow >= M) arow = M - 1;
        const float4* Ap = (const float4*)(A + (size_t)arow * 128);
#pragma unroll
        for (int i = 0; i < 8; i++) {
            int col = q * 32 + i * 4;
            float4 v = Ap[col >> 2];
            uint32_t h01, l01, h23, l23;
            split2(v.x, v.y, h01, l01);
            split2(v.z, v.w, h23, l23);
            int o = m * WS + (col >> 1);
            sAh[o] = h01; sAh[o + 1] = h23;
            sAl[o] = l01; sAl[o + 1] = l23;
        }
    }
    __syncthreads();

    float c[2][4][4];
#pragma unroll
    for (int mi = 0; mi < 2; mi++)
#pragma unroll
        for (int ni = 0; ni < 4; ni++)
#pragma unroll
            for (int r = 0; r < 4; r++) c[mi][ni][r] = 0.0f;

    // ldmatrix per-lane base addresses (kk = 0), advanced 32B per kk.
    // A (per mi): lanes 0-7 -> m0-7 k[0:8), 8-15 -> m8-15 k[0:8),
    //             16-23 -> m0-7 k[8:16), 24-31 -> m8-15 k[8:16)  => regs a0..a3
    // B (per ni-pair): lanes 0-7 -> n0-7 k[0:8), 8-15 -> n0-7 k[8:16),
    //                  16-23 -> n8-15 k[0:8), 24-31 -> n8-15 k[8:16) => {b0,b1} x2
    uint32_t aAddr[2], bAddr[2];
    {
        uint32_t baseA = (uint32_t)__cvta_generic_to_shared(sAh);
        uint32_t baseW = (uint32_t)__cvta_generic_to_shared(sWh);
        int am = wm * 32 + (lane & 15);
        int ac = lane >> 4;                       // k chunk
#pragma unroll
        for (int mi = 0; mi < 2; mi++)
            aAddr[mi] = baseA + (am + mi * 16) * ROWB + ac * 16;
        int bn = (lane & 7) + ((lane >> 4) << 3); // n within 16
        int bc = (lane >> 3) & 1;                 // k chunk
#pragma unroll
        for (int p = 0; p < 2; p++)
            bAddr[p] = baseW + (wn * 32 + p * 16 + bn) * ROWB + bc * 16;
    }

#pragma unroll
    for (int kk = 0; kk < 8; kk++) {
        uint32_t ah[2][4], al[2][4], bh[2][4], bl[2][4];
#pragma unroll
        for (int mi = 0; mi < 2; mi++) {
            uint32_t ad = aAddr[mi] + kk * 32;
            ldsm4(ah[mi][0], ah[mi][1], ah[mi][2], ah[mi][3], ad);
            ldsm4(al[mi][0], al[mi][1], al[mi][2], al[mi][3], ad + LO_A);
        }
#pragma unroll
        for (int p = 0; p < 2; p++) {
            uint32_t bd = bAddr[p] + kk * 32;
            ldsm4(bh[p][0], bh[p][1], bh[p][2], bh[p][3], bd);
            ldsm4(bl[p][0], bl[p][1], bl[p][2], bl[p][3], bd + LO_W);
        }
#pragma unroll
        for (int mi = 0; mi < 2; mi++)
#pragma unroll
            for (int ni = 0; ni < 4; ni++) {
                const uint32_t* pbh = &bh[ni >> 1][(ni & 1) * 2];
                const uint32_t* pbl = &bl[ni >> 1][(ni & 1) * 2];
                mma_bf16(c[mi][ni], ah[mi], pbh);
                mma_bf16(c[mi][ni], ah[mi], pbl);
                mma_bf16(c[mi][ni], al[mi], pbh);
            }
    }

    // epilogue: c0=(r,2c), c1=(r,2c+1), c2=(r+8,2c), c3=(r+8,2c+1)
#pragma unroll
    for (int mi = 0; mi < 2; mi++) {
#pragma unroll
        for (int ni = 0; ni < 4; ni++) {
            int gr = row0 + wm * 32 + mi * 16 + l28;
            int gc = wn * 32 + ni * 8 + 2 * l4;
            float b0 = bias[gc], b1 = bias[gc + 1];
            if (gr < M) {
                float2 o;
                o.x = c[mi][ni][0] + b0;
                o.y = c[mi][ni][1] + b1;
                if (RESID) {
                    float2 r = *(const float2*)(R + (size_t)gr * 128 + gc);
                    o.x += r.x; o.y += r.y;
                }
                *(float2*)(C + (size_t)gr * 128 + gc) = o;
            }
            if (gr + 8 < M) {
                float2 o;
                o.x = c[mi][ni][2] + b0;
                o.y = c[mi][ni][3] + b1;
                if (RESID) {
                    float2 r = *(const float2*)(R + (size_t)(gr + 8) * 128 + gc);
                    o.x += r.x; o.y += r.y;
                }
                *(float2*)(C + (size_t)(gr + 8) * 128 + gc) = o;
            }
        }
    }
}

// ---------------- fused per-node attention (one warp per node, 4-edge unroll) ----------------
__global__ __launch_bounds__(256) void k_attn(int NN) {
    int warp = threadIdx.x >> 5;
    int lane = threadIdx.x & 31;
    int n = blockIdx.x * 8 + warp;
    if (n >= NN) return;

    const float4* Q4 = (const float4*)g_Q;
    const float4* K4 = (const float4*)g_K;
    const float4* V4 = (const float4*)g_V;

    float4 q = Q4[(size_t)n * 32 + lane];
    float z = 0.0f;
    float ax = 0.0f, ay = 0.0f, az = 0.0f, aw = 0.0f;
    const float sc = 0.17677669529663687f;  // 1/sqrt(32)

    int beg = g_offset[n];
    int end = g_offset[n + 1];
    int j = beg;
    for (; j + 4 <= end; j += 4) {
        int d0 = g_edge_dst[j + 0];
        int d1 = g_edge_dst[j + 1];
        int d2 = g_edge_dst[j + 2];
        int d3 = g_edge_dst[j + 3];
        float4 k0 = K4[(size_t)d0 * 32 + lane];
        float4 k1 = K4[(size_t)d1 * 32 + lane];
        float4 k2 = K4[(size_t)d2 * 32 + lane];
        float4 k3 = K4[(size_t)d3 * 32 + lane];
        float4 v0 = V4[(size_t)d0 * 32 + lane];
        float4 v1 = V4[(size_t)d1 * 32 + lane];
        float4 v2 = V4[(size_t)d2 * 32 + lane];
        float4 v3 = V4[(size_t)d3 * 32 + lane];

        float p0 = q.x * k0.x + q.y * k0.y + q.z * k0.z + q.w * k0.w;
        float p1 = q.x * k1.x + q.y * k1.y + q.z * k1.z + q.w * k1.w;
        float p2 = q.x * k2.x + q.y * k2.y + q.z * k2.z + q.w * k2.w;
        float p3 = q.x * k3.x + q.y * k3.y + q.z * k3.z + q.w * k3.w;
#pragma unroll
        for (int o = 1; o <= 4; o <<= 1) {
            p0 += __shfl_xor_sync(0xffffffffu, p0, o);
            p1 += __shfl_xor_sync(0xffffffffu, p1, o);
            p2 += __shfl_xor_sync(0xffffffffu, p2, o);
            p3 += __shfl_xor_sync(0xffffffffu, p3, o);
        }
        float e0 = __expf(p0 * sc);
        float e1 = __expf(p1 * sc);
        float e2 = __expf(p2 * sc);
        float e3 = __expf(p3 * sc);
        z += (e0 + e1) + (e2 + e3);
        ax += e0 * v0.x + e1 * v1.x + e2 * v2.x + e3 * v3.x;
        ay += e0 * v0.y + e1 * v1.y + e2 * v2.y + e3 * v3.y;
        az += e0 * v0.z + e1 * v1.z + e2 * v2.z + e3 * v3.z;
        aw += e0 * v0.w + e1 * v1.w + e2 * v2.w + e3 * v3.w;
    }
    for (; j < end; j++) {
        int d = g_edge_dst[j];
        float4 k4 = K4[(size_t)d * 32 + lane];
        float4 v4 = V4[(size_t)d * 32 + lane];
        float p = q.x * k4.x + q.y * k4.y + q.z * k4.z + q.w * k4.w;
        p += __shfl_xor_sync(0xffffffffu, p, 1);
        p += __shfl_xor_sync(0xffffffffu, p, 2);
        p += __shfl_xor_sync(0xffffffffu, p, 4);
        float e = __expf(p * sc);
        z += e;
        ax += e * v4.x; ay += e * v4.y; az += e * v4.z; aw += e * v4.w;
    }
    float inv = (z > 0.0f) ? (1.0f / z) : 0.0f;
    float4 o;
    o.x = ax * inv; o.y = ay * inv; o.z = az * inv; o.w = aw * inv;
    ((float4*)g_attn)[(size_t)n * 32 + lane] = o;
}

// ---------------- launch ----------------
extern "C" void kernel_launch(void* const* d_in, const int* in_sizes, int n_in,
                              void* d_out, int out_size)
{
    const float* x_node = (const float*)d_in[0];
    const float* x_edge = (const float*)d_in[1];
    const int*   src    = (const int*)d_in[2];
    const int*   dst    = (const int*)d_in[3];
    const float* Wq     = (const float*)d_in[4];
    const float* bq     = (const float*)d_in[5];
    const float* Wk     = (const float*)d_in[6];
    const float* bk     = (const float*)d_in[7];
    const float* Wv     = (const float*)d_in[8];
    const float* bv     = (const float*)d_in[9];
    const float* Wo     = (const float*)d_in[10];
    const float* bo     = (const float*)d_in[11];
    float* out = (float*)d_out;

    int NN = in_sizes[0] / 128;
    int ME = in_sizes[1] / 128;
    int E  = in_sizes[2];

    float *Qp, *Kp, *Vp, *Ap;
    uint4* Wspp;
    cudaGetSymbolAddress((void**)&Qp, g_Q);
    cudaGetSymbolAddress((void**)&Kp, g_K);
    cudaGetSymbolAddress((void**)&Vp, g_V);
    cudaGetSymbolAddress((void**)&Ap, g_attn);
    cudaGetSymbolAddress((void**)&Wspp, g_Wsp);
    const size_t wstride = (size_t)2 * 128 * 136 * sizeof(__nv_bfloat16) / sizeof(uint4);

    cudaFuncSetAttribute(k_gemmB<false>, cudaFuncAttributeMaxDynamicSharedMemorySize, GEMM_SMEM);
    cudaFuncSetAttribute(k_gemmB<true>,  cudaFuncAttributeMaxDynamicSharedMemorySize, GEMM_SMEM);

    k_zero<<<(NN + 255) / 256, 256>>>(NN);
    k_splitW<<<dim3(64, 4), 256>>>(Wq, Wk, Wv, Wo);
    k_gemmB<false><<<(NN + 63) / 64, 256, GEMM_SMEM>>>(x_node, Wspp + 0 * wstride, bq, nullptr, Qp, NN);
    k_gemmB<false><<<(ME + 63) / 64, 256, GEMM_SMEM>>>(x_edge, Wspp + 1 * wstride, bk, nullptr, Kp, ME);
    k_gemmB<false><<<(ME + 63) / 64, 256, GEMM_SMEM>>>(x_edge, Wspp + 2 * wstride, bv, nullptr, Vp, ME);
    k_hist<<<(E + 255) / 256, 256>>>(src, E);
    k_scan<<<1, 1024>>>(NN);
    k_scatter<<<(E + 255) / 256, 256>>>(src, dst, E);
    k_attn<<<(NN + 7) / 8, 256>>>(NN);
    k_gemmB<true><<<(NN + 63) / 64, 256, GEMM_SMEM>>>(Ap, Wspp + 3 * wstride, bo, x_node, out, NN);
}

// round 11
// speedup vs baseline: 1.4258x; 1.0407x over previous
#include <cuda_runtime.h>
#include <cuda_bf16.h>
#include <cuda_fp16.h>
#include <cstdint>

#define NN_MAX 50000
#define ME_MAX 20000
#define E_MAX  800000

// ---------------- scratch (static device globals; no allocation) ----------------
__device__ float g_Q[NN_MAX * 128];
__device__ __align__(16) __half g_Kh[ME_MAX * 128];
__device__ __align__(16) __half g_Vh[ME_MAX * 128];
__device__ float g_attn[NN_MAX * 128];
__device__ int   g_count[NN_MAX];
__device__ int   g_offset[NN_MAX + 1];
__device__ int   g_cursor[NN_MAX];
__device__ int   g_edge_dst[E_MAX];
// split weights: [which][hi/lo][n*136 + k]  (bf16, transposed to [n][k], row stride 136)
__device__ __align__(16) __nv_bfloat16 g_Wsp[4][2][128 * 136];

// ---------------- CSR build ----------------
__global__ void k_zero(int n) {
    int i = blockIdx.x * blockDim.x + threadIdx.x;
    if (i < n) g_count[i] = 0;
}

__global__ void k_hist(const int* __restrict__ src, int E) {
    int e = blockIdx.x * blockDim.x + threadIdx.x;
    if (e < E) atomicAdd(&g_count[src[e]], 1);
}

__global__ void k_scan(int n) {
    __shared__ int sm[1024];
    int t = threadIdx.x;
    int chunk = (n + 1023) >> 10;
    int b = t * chunk;
    int e = min(b + chunk, n);
    int s = 0;
    for (int i = b; i < e; i++) s += g_count[i];
    sm[t] = s;
    __syncthreads();
    for (int o = 1; o < 1024; o <<= 1) {
        int v = (t >= o) ? sm[t - o] : 0;
        __syncthreads();
        sm[t] += v;
        __syncthreads();
    }
    int run = (t == 0) ? 0 : sm[t - 1];
    for (int i = b; i < e; i++) {
        int c = g_count[i];
        g_offset[i] = run;
        g_cursor[i] = run;
        run += c;
    }
    if (t == 1023) g_offset[n] = sm[1023];
}

__global__ void k_scatter(const int* __restrict__ src, const int* __restrict__ dst, int E) {
    int e = blockIdx.x * blockDim.x + threadIdx.x;
    if (e < E) {
        int p = atomicAdd(&g_cursor[src[e]], 1);
        g_edge_dst[p] = dst[e];
    }
}

// ---------------- weight split: W[k][n] fp32 -> bf16 hi/lo, transposed [n][k] ----------------
__global__ void k_splitW(const float* __restrict__ W0, const float* __restrict__ W1,
                         const float* __restrict__ W2, const float* __restrict__ W3) {
    int w = blockIdx.y;
    const float* W = (w == 0) ? W0 : (w == 1) ? W1 : (w == 2) ? W2 : W3;
    int gid = blockIdx.x * 256 + threadIdx.x;   // 0..16383
    int n = gid >> 7;
    int k = gid & 127;
    float x = W[k * 128 + n];
    __nv_bfloat16 h = __float2bfloat16_rn(x);
    __nv_bfloat16 l = __float2bfloat16_rn(x - __bfloat162float(h));
    g_Wsp[w][0][n * 136 + k] = h;
    g_Wsp[w][1][n * 136 + k] = l;
}

// ---------------- bf16 3-term tensor-core GEMM ----------------
// MODE 0: fp32 out (+bias).  MODE 1: fp16 out (+bias).  MODE 2: fp32 out (+bias+resid).

__device__ __forceinline__ void mma_bf16(float* c, const uint32_t* a, const uint32_t* b) {
    asm volatile(
        "mma.sync.aligned.m16n8k16.row.col.f32.bf16.bf16.f32 "
        "{%0,%1,%2,%3}, {%4,%5,%6,%7}, {%8,%9}, {%0,%1,%2,%3};"
        : "+f"(c[0]), "+f"(c[1]), "+f"(c[2]), "+f"(c[3])
        : "r"(a[0]), "r"(a[1]), "r"(a[2]), "r"(a[3]), "r"(b[0]), "r"(b[1]));
}

__device__ __forceinline__ void ldsm4(uint32_t& r0, uint32_t& r1, uint32_t& r2, uint32_t& r3,
                                      uint32_t addr) {
    asm volatile("ldmatrix.sync.aligned.m8n8.x4.shared.b16 {%0,%1,%2,%3}, [%4];"
                 : "=r"(r0), "=r"(r1), "=r"(r2), "=r"(r3) : "r"(addr));
}

__device__ __forceinline__ void split2(float x, float y, uint32_t& h, uint32_t& l) {
    __nv_bfloat162 hb = __floats2bfloat162_rn(x, y);
    float hx = __bfloat162float(hb.x);
    float hy = __bfloat162float(hb.y);
    __nv_bfloat162 lb = __floats2bfloat162_rn(x - hx, y - hy);
    h = *(uint32_t*)&hb;
    l = *(uint32_t*)&lb;
}

#define WS 68  // row stride in b32 units (136 bf16, 272 bytes)
#define GEMM_SMEM ((2 * 128 * WS + 2 * 64 * WS) * 4)  // 104448 bytes
#define ROWB (WS * 4)                                  // 272 bytes per row
#define LO_W (128 * WS * 4)                            // byte offset sWh -> sWl
#define LO_A (64 * WS * 4)                             // byte offset sAh -> sAl

template <int MODE>
__global__ __launch_bounds__(256, 2) void k_gemmB(
    const float* __restrict__ A, const uint4* __restrict__ Wsp,
    const float* __restrict__ bias, const float* __restrict__ R,
    void* __restrict__ Cout, int M)
{
    extern __shared__ uint32_t sm[];
    uint32_t* sWh = sm;                      // 128*68
    uint32_t* sAh = sm + 2 * 128 * WS;       // 64*68
    uint32_t* sAl = sm + 2 * 128 * WS + 64 * WS;

    const int t = threadIdx.x;
    const int lane = t & 31, warp = t >> 5;
    const int l4 = lane & 3, l28 = lane >> 2;
    const int wm = warp & 1;    // x32 rows
    const int wn = warp >> 1;   // x32 cols
    const int row0 = blockIdx.x * 64;

    // stage W (hi+lo contiguous in global): 4352 uint4 -> 17/thread
    {
        uint4* dW = (uint4*)sWh;
#pragma unroll
        for (int i = 0; i < 17; i++)
            dW[t + i * 256] = Wsp[t + i * 256];
    }
    // stage A: 64 rows x 128 cols fp32, convert to bf16 hi/lo.  4 threads/row, 8 float4 each.
    {
        int m = t >> 2;
        int q = t & 3;
        int arow = row0 + m;
        if (arow >= M) arow = M - 1;
        const float4* Ap = (const float4*)(A + (size_t)arow * 128);
#pragma unroll
        for (int i = 0; i < 8; i++) {
            int col = q * 32 + i * 4;
            float4 v = Ap[col >> 2];
            uint32_t h01, l01, h23, l23;
            split2(v.x, v.y, h01, l01);
            split2(v.z, v.w, h23, l23);
            int o = m * WS + (col >> 1);
            sAh[o] = h01; sAh[o + 1] = h23;
            sAl[o] = l01; sAl[o + 1] = l23;
        }
    }
    __syncthreads();

    float c[2][4][4];
#pragma unroll
    for (int mi = 0; mi < 2; mi++)
#pragma unroll
        for (int ni = 0; ni < 4; ni++)
#pragma unroll
            for (int r = 0; r < 4; r++) c[mi][ni][r] = 0.0f;

    uint32_t aAddr[2], bAddr[2];
    {
        uint32_t baseA = (uint32_t)__cvta_generic_to_shared(sAh);
        uint32_t baseW = (uint32_t)__cvta_generic_to_shared(sWh);
        int am = wm * 32 + (lane & 15);
        int ac = lane >> 4;                       // k chunk
#pragma unroll
        for (int mi = 0; mi < 2; mi++)
            aAddr[mi] = baseA + (am + mi * 16) * ROWB + ac * 16;
        int bn = (lane & 7) + ((lane >> 4) << 3); // n within 16
        int bc = (lane >> 3) & 1;                 // k chunk
#pragma unroll
        for (int p = 0; p < 2; p++)
            bAddr[p] = baseW + (wn * 32 + p * 16 + bn) * ROWB + bc * 16;
    }

#pragma unroll
    for (int kk = 0; kk < 8; kk++) {
        uint32_t ah[2][4], al[2][4], bh[2][4], bl[2][4];
#pragma unroll
        for (int mi = 0; mi < 2; mi++) {
            uint32_t ad = aAddr[mi] + kk * 32;
            ldsm4(ah[mi][0], ah[mi][1], ah[mi][2], ah[mi][3], ad);
            ldsm4(al[mi][0], al[mi][1], al[mi][2], al[mi][3], ad + LO_A);
        }
#pragma unroll
        for (int p = 0; p < 2; p++) {
            uint32_t bd = bAddr[p] + kk * 32;
            ldsm4(bh[p][0], bh[p][1], bh[p][2], bh[p][3], bd);
            ldsm4(bl[p][0], bl[p][1], bl[p][2], bl[p][3], bd + LO_W);
        }
#pragma unroll
        for (int mi = 0; mi < 2; mi++)
#pragma unroll
            for (int ni = 0; ni < 4; ni++) {
                const uint32_t* pbh = &bh[ni >> 1][(ni & 1) * 2];
                const uint32_t* pbl = &bl[ni >> 1][(ni & 1) * 2];
                mma_bf16(c[mi][ni], ah[mi], pbh);
                mma_bf16(c[mi][ni], ah[mi], pbl);
                mma_bf16(c[mi][ni], al[mi], pbh);
            }
    }

    // epilogue: c0=(r,2c), c1=(r,2c+1), c2=(r+8,2c), c3=(r+8,2c+1)
#pragma unroll
    for (int mi = 0; mi < 2; mi++) {
#pragma unroll
        for (int ni = 0; ni < 4; ni++) {
            int gr = row0 + wm * 32 + mi * 16 + l28;
            int gc = wn * 32 + ni * 8 + 2 * l4;
            float b0 = bias[gc], b1 = bias[gc + 1];
            if (gr < M) {
                float ox = c[mi][ni][0] + b0;
                float oy = c[mi][ni][1] + b1;
                if (MODE == 2) {
                    float2 r = *(const float2*)(R + (size_t)gr * 128 + gc);
                    ox += r.x; oy += r.y;
                }
                if (MODE == 1) {
                    ((__half2*)Cout)[(size_t)gr * 64 + (gc >> 1)] = __floats2half2_rn(ox, oy);
                } else {
                    *(float2*)((float*)Cout + (size_t)gr * 128 + gc) = make_float2(ox, oy);
                }
            }
            if (gr + 8 < M) {
                float ox = c[mi][ni][2] + b0;
                float oy = c[mi][ni][3] + b1;
                if (MODE == 2) {
                    float2 r = *(const float2*)(R + (size_t)(gr + 8) * 128 + gc);
                    ox += r.x; oy += r.y;
                }
                if (MODE == 1) {
                    ((__half2*)Cout)[(size_t)(gr + 8) * 64 + (gc >> 1)] = __floats2half2_rn(ox, oy);
                } else {
                    *(float2*)((float*)Cout + (size_t)(gr + 8) * 128 + gc) = make_float2(ox, oy);
                }
            }
        }
    }
}

// ---------------- fused per-node attention (one warp per node, 4-edge unroll, fp16 K/V) ----------------
__device__ __forceinline__ float dot_kh(const float4& q, uint2 u) {
    float2 a = __half22float2(*(__half2*)&u.x);
    float2 b = __half22float2(*(__half2*)&u.y);
    return q.x * a.x + q.y * a.y + q.z * b.x + q.w * b.y;
}

__global__ __launch_bounds__(256) void k_attn(int NN) {
    int warp = threadIdx.x >> 5;
    int lane = threadIdx.x & 31;
    int n = blockIdx.x * 8 + warp;
    if (n >= NN) return;

    const float4* Q4 = (const float4*)g_Q;
    const uint2* K2 = (const uint2*)g_Kh;   // row = 32 uint2 (128 halves)
    const uint2* V2 = (const uint2*)g_Vh;

    float4 q = Q4[(size_t)n * 32 + lane];   // lane holds dims [lane*4, lane*4+4); head = lane/8
    float z = 0.0f;
    float ax = 0.0f, ay = 0.0f, az = 0.0f, aw = 0.0f;
    const float sc = 0.17677669529663687f;  // 1/sqrt(32)

    int beg = g_offset[n];
    int end = g_offset[n + 1];
    int j = beg;
    for (; j + 4 <= end; j += 4) {
        int d0 = g_edge_dst[j + 0];
        int d1 = g_edge_dst[j + 1];
        int d2 = g_edge_dst[j + 2];
        int d3 = g_edge_dst[j + 3];
        uint2 k0 = K2[(size_t)d0 * 32 + lane];
        uint2 k1 = K2[(size_t)d1 * 32 + lane];
        uint2 k2 = K2[(size_t)d2 * 32 + lane];
        uint2 k3 = K2[(size_t)d3 * 32 + lane];
        uint2 v0 = V2[(size_t)d0 * 32 + lane];
        uint2 v1 = V2[(size_t)d1 * 32 + lane];
        uint2 v2 = V2[(size_t)d2 * 32 + lane];
        uint2 v3 = V2[(size_t)d3 * 32 + lane];

        float p0 = dot_kh(q, k0);
        float p1 = dot_kh(q, k1);
        float p2 = dot_kh(q, k2);
        float p3 = dot_kh(q, k3);
#pragma unroll
        for (int o = 1; o <= 4; o <<= 1) {
            p0 += __shfl_xor_sync(0xffffffffu, p0, o);
            p1 += __shfl_xor_sync(0xffffffffu, p1, o);
            p2 += __shfl_xor_sync(0xffffffffu, p2, o);
            p3 += __shfl_xor_sync(0xffffffffu, p3, o);
        }
        float e0 = __expf(p0 * sc);
        float e1 = __expf(p1 * sc);
        float e2 = __expf(p2 * sc);
        float e3 = __expf(p3 * sc);
        z += (e0 + e1) + (e2 + e3);
        float2 va, vb;
        va = __half22float2(*(__half2*)&v0.x); vb = __half22float2(*(__half2*)&v0.y);
        ax += e0 * va.x; ay += e0 * va.y; az += e0 * vb.x; aw += e0 * vb.y;
        va = __half22float2(*(__half2*)&v1.x); vb = __half22float2(*(__half2*)&v1.y);
        ax += e1 * va.x; ay += e1 * va.y; az += e1 * vb.x; aw += e1 * vb.y;
        va = __half22float2(*(__half2*)&v2.x); vb = __half22float2(*(__half2*)&v2.y);
        ax += e2 * va.x; ay += e2 * va.y; az += e2 * vb.x; aw += e2 * vb.y;
        va = __half22float2(*(__half2*)&v3.x); vb = __half22float2(*(__half2*)&v3.y);
        ax += e3 * va.x; ay += e3 * va.y; az += e3 * vb.x; aw += e3 * vb.y;
    }
    for (; j < end; j++) {
        int d = g_edge_dst[j];
        uint2 ku = K2[(size_t)d * 32 + lane];
        uint2 vu = V2[(size_t)d * 32 + lane];
        float p = dot_kh(q, ku);
        p += __shfl_xor_sync(0xffffffffu, p, 1);
        p += __shfl_xor_sync(0xffffffffu, p, 2);
        p += __shfl_xor_sync(0xffffffffu, p, 4);
        float e = __expf(p * sc);
        z += e;
        float2 va = __half22float2(*(__half2*)&vu.x);
        float2 vb = __half22float2(*(__half2*)&vu.y);
        ax += e * va.x; ay += e * va.y; az += e * vb.x; aw += e * vb.y;
    }
    float inv = (z > 0.0f) ? (1.0f / z) : 0.0f;
    float4 o;
    o.x = ax * inv; o.y = ay * inv; o.z = az * inv; o.w = aw * inv;
    ((float4*)g_attn)[(size_t)n * 32 + lane] = o;
}

// ---------------- launch ----------------
extern "C" void kernel_launch(void* const* d_in, const int* in_sizes, int n_in,
                              void* d_out, int out_size)
{
    const float* x_node = (const float*)d_in[0];
    const float* x_edge = (const float*)d_in[1];
    const int*   src    = (const int*)d_in[2];
    const int*   dst    = (const int*)d_in[3];
    const float* Wq     = (const float*)d_in[4];
    const float* bq     = (const float*)d_in[5];
    const float* Wk     = (const float*)d_in[6];
    const float* bk     = (const float*)d_in[7];
    const float* Wv     = (const float*)d_in[8];
    const float* bv     = (const float*)d_in[9];
    const float* Wo     = (const float*)d_in[10];
    const float* bo     = (const float*)d_in[11];
    float* out = (float*)d_out;

    int NN = in_sizes[0] / 128;
    int ME = in_sizes[1] / 128;
    int E  = in_sizes[2];

    float *Qp, *Ap;
    __half *Khp, *Vhp;
    uint4* Wspp;
    cudaGetSymbolAddress((void**)&Qp, g_Q);
    cudaGetSymbolAddress((void**)&Khp, g_Kh);
    cudaGetSymbolAddress((void**)&Vhp, g_Vh);
    cudaGetSymbolAddress((void**)&Ap, g_attn);
    cudaGetSymbolAddress((void**)&Wspp, g_Wsp);
    const size_t wstride = (size_t)2 * 128 * 136 * sizeof(__nv_bfloat16) / sizeof(uint4);

    cudaFuncSetAttribute(k_gemmB<0>, cudaFuncAttributeMaxDynamicSharedMemorySize, GEMM_SMEM);
    cudaFuncSetAttribute(k_gemmB<1>, cudaFuncAttributeMaxDynamicSharedMemorySize, GEMM_SMEM);
    cudaFuncSetAttribute(k_gemmB<2>, cudaFuncAttributeMaxDynamicSharedMemorySize, GEMM_SMEM);

    k_zero<<<(NN + 255) / 256, 256>>>(NN);
    k_splitW<<<dim3(64, 4), 256>>>(Wq, Wk, Wv, Wo);
    k_gemmB<0><<<(NN + 63) / 64, 256, GEMM_SMEM>>>(x_node, Wspp + 0 * wstride, bq, nullptr, Qp, NN);
    k_gemmB<1><<<(ME + 63) / 64, 256, GEMM_SMEM>>>(x_edge, Wspp + 1 * wstride, bk, nullptr, Khp, ME);
    k_gemmB<1><<<(ME + 63) / 64, 256, GEMM_SMEM>>>(x_edge, Wspp + 2 * wstride, bv, nullptr, Vhp, ME);
    k_hist<<<(E + 255) / 256, 256>>>(src, E);
    k_scan<<<1, 1024>>>(NN);
    k_scatter<<<(E + 255) / 256, 256>>>(src, dst, E);
    k_attn<<<(NN + 7) / 8, 256>>>(NN);
    k_gemmB<2><<<(NN + 63) / 64, 256, GEMM_SMEM>>>(Ap, Wspp + 3 * wstride, bo, x_node, out, NN);
}

// round 12
// speedup vs baseline: 1.5384x; 1.0789x over previous
#include <cuda_runtime.h>
#include <cuda_fp16.h>
#include <cstdint>

#define NN_MAX 50000
#define ME_MAX 20000
#define E_MAX  800000

// ---------------- scratch (static device globals; no allocation) ----------------
__device__ float g_Q[NN_MAX * 128];
__device__ __align__(16) __half g_Kh[ME_MAX * 128];
__device__ __align__(16) __half g_Vh[ME_MAX * 128];
__device__ float g_attn[NN_MAX * 128];
__device__ int   g_count[NN_MAX];
__device__ int   g_offset[NN_MAX + 1];
__device__ int   g_cursor[NN_MAX];
__device__ int   g_edge_dst[E_MAX];
// split weights: [which][hi/lo][n*136 + k]  (fp16, transposed to [n][k], row stride 136)
__device__ __align__(16) __half g_Wsp[4][2][128 * 136];

// ---------------- CSR build ----------------
__global__ void k_zero(int n) {
    int i = blockIdx.x * blockDim.x + threadIdx.x;
    if (i < n) g_count[i] = 0;
}

__global__ void k_hist(const int* __restrict__ src, int E) {
    int e = blockIdx.x * blockDim.x + threadIdx.x;
    if (e < E) atomicAdd(&g_count[src[e]], 1);
}

__global__ void k_scan(int n) {
    __shared__ int sm[1024];
    int t = threadIdx.x;
    int chunk = (n + 1023) >> 10;
    int b = t * chunk;
    int e = min(b + chunk, n);
    int s = 0;
    for (int i = b; i < e; i++) s += g_count[i];
    sm[t] = s;
    __syncthreads();
    for (int o = 1; o < 1024; o <<= 1) {
        int v = (t >= o) ? sm[t - o] : 0;
        __syncthreads();
        sm[t] += v;
        __syncthreads();
    }
    int run = (t == 0) ? 0 : sm[t - 1];
    for (int i = b; i < e; i++) {
        int c = g_count[i];
        g_offset[i] = run;
        g_cursor[i] = run;
        run += c;
    }
    if (t == 1023) g_offset[n] = sm[1023];
}

__global__ void k_scatter(const int* __restrict__ src, const int* __restrict__ dst, int E) {
    int e = blockIdx.x * blockDim.x + threadIdx.x;
    if (e < E) {
        int p = atomicAdd(&g_cursor[src[e]], 1);
        g_edge_dst[p] = dst[e];
    }
}

// ---------------- weight split: W[k][n] fp32 -> fp16 hi/lo, transposed [n][k] ----------------
__global__ void k_splitW(const float* __restrict__ W0, const float* __restrict__ W1,
                         const float* __restrict__ W2, const float* __restrict__ W3) {
    int w = blockIdx.y;
    const float* W = (w == 0) ? W0 : (w == 1) ? W1 : (w == 2) ? W2 : W3;
    int gid = blockIdx.x * 256 + threadIdx.x;   // 0..16383
    int n = gid >> 7;
    int k = gid & 127;
    float x = W[k * 128 + n];
    __half h = __float2half_rn(x);
    __half l = __float2half_rn(x - __half2float(h));
    g_Wsp[w][0][n * 136 + k] = h;
    g_Wsp[w][1][n * 136 + k] = l;
}

// ---------------- fp16 2-term tensor-core GEMM ----------------
// C[M,128] = fp16(A[M,128]) @ (Wh + Wl) + bias (+R).
// MODE 0: fp32 out (+bias).  MODE 1: fp16 out (+bias).  MODE 2: fp32 out (+bias+resid).
// Per CTA: 64 rows x 128 cols, full K in smem, one barrier, 8 unrolled k-steps,
// fragments via ldmatrix.x4: per warp per kk -> 2 A-ldsm + 4 B-ldsm, 16 MMAs.

__device__ __forceinline__ void mma_fp16(float* c, const uint32_t* a, const uint32_t* b) {
    asm volatile(
        "mma.sync.aligned.m16n8k16.row.col.f32.f16.f16.f32 "
        "{%0,%1,%2,%3}, {%4,%5,%6,%7}, {%8,%9}, {%0,%1,%2,%3};"
        : "+f"(c[0]), "+f"(c[1]), "+f"(c[2]), "+f"(c[3])
        : "r"(a[0]), "r"(a[1]), "r"(a[2]), "r"(a[3]), "r"(b[0]), "r"(b[1]));
}

__device__ __forceinline__ void ldsm4(uint32_t& r0, uint32_t& r1, uint32_t& r2, uint32_t& r3,
                                      uint32_t addr) {
    asm volatile("ldmatrix.sync.aligned.m8n8.x4.shared.b16 {%0,%1,%2,%3}, [%4];"
                 : "=r"(r0), "=r"(r1), "=r"(r2), "=r"(r3) : "r"(addr));
}

#define WS 68  // row stride in b32 units (136 fp16, 272 bytes)
#define GEMM_SMEM ((2 * 128 * WS + 64 * WS) * 4)  // 87040 bytes
#define ROWB (WS * 4)                              // 272 bytes per row
#define LO_W (128 * WS * 4)                        // byte offset Wh -> Wl

template <int MODE>
__global__ __launch_bounds__(256, 2) void k_gemmB(
    const float* __restrict__ A, const uint4* __restrict__ Wsp,
    const float* __restrict__ bias, const float* __restrict__ R,
    void* __restrict__ Cout, int M)
{
    extern __shared__ uint32_t sm[];
    uint32_t* sWh = sm;                 // 2*128*68 (hi then lo)
    uint32_t* sA  = sm + 2 * 128 * WS;  // 64*68 (fp16 rows)

    const int t = threadIdx.x;
    const int lane = t & 31, warp = t >> 5;
    const int l4 = lane & 3, l28 = lane >> 2;
    const int wm = warp & 1;    // x32 rows
    const int wn = warp >> 1;   // x32 cols
    const int row0 = blockIdx.x * 64;

    // stage W (hi+lo contiguous in global): 4352 uint4 -> 17/thread
    {
        uint4* dW = (uint4*)sWh;
#pragma unroll
        for (int i = 0; i < 17; i++)
            dW[t + i * 256] = Wsp[t + i * 256];
    }
    // stage A: 64 rows x 128 cols fp32 -> fp16.  4 threads/row, 8 float4 each.
    {
        int m = t >> 2;
        int q = t & 3;
        int arow = row0 + m;
        if (arow >= M) arow = M - 1;
        const float4* Ap = (const float4*)(A + (size_t)arow * 128);
#pragma unroll
        for (int i = 0; i < 8; i++) {
            int col = q * 32 + i * 4;
            float4 v = Ap[col >> 2];
            __half2 h01 = __floats2half2_rn(v.x, v.y);
            __half2 h23 = __floats2half2_rn(v.z, v.w);
            int o = m * WS + (col >> 1);
            sA[o]     = *(uint32_t*)&h01;
            sA[o + 1] = *(uint32_t*)&h23;
        }
    }
    __syncthreads();

    float c[2][4][4];
#pragma unroll
    for (int mi = 0; mi < 2; mi++)
#pragma unroll
        for (int ni = 0; ni < 4; ni++)
#pragma unroll
            for (int r = 0; r < 4; r++) c[mi][ni][r] = 0.0f;

    uint32_t aAddr[2], bAddr[2];
    {
        uint32_t baseA = (uint32_t)__cvta_generic_to_shared(sA);
        uint32_t baseW = (uint32_t)__cvta_generic_to_shared(sWh);
        int am = wm * 32 + (lane & 15);
        int ac = lane >> 4;                       // k chunk
#pragma unroll
        for (int mi = 0; mi < 2; mi++)
            aAddr[mi] = baseA + (am + mi * 16) * ROWB + ac * 16;
        int bn = (lane & 7) + ((lane >> 4) << 3); // n within 16
        int bc = (lane >> 3) & 1;                 // k chunk
#pragma unroll
        for (int p = 0; p < 2; p++)
            bAddr[p] = baseW + (wn * 32 + p * 16 + bn) * ROWB + bc * 16;
    }

#pragma unroll
    for (int kk = 0; kk < 8; kk++) {
        uint32_t ah[2][4], bh[2][4], bl[2][4];
#pragma unroll
        for (int mi = 0; mi < 2; mi++) {
            uint32_t ad = aAddr[mi] + kk * 32;
            ldsm4(ah[mi][0], ah[mi][1], ah[mi][2], ah[mi][3], ad);
        }
#pragma unroll
        for (int p = 0; p < 2; p++) {
            uint32_t bd = bAddr[p] + kk * 32;
            ldsm4(bh[p][0], bh[p][1], bh[p][2], bh[p][3], bd);
            ldsm4(bl[p][0], bl[p][1], bl[p][2], bl[p][3], bd + LO_W);
        }
#pragma unroll
        for (int mi = 0; mi < 2; mi++)
#pragma unroll
            for (int ni = 0; ni < 4; ni++) {
                const uint32_t* pbh = &bh[ni >> 1][(ni & 1) * 2];
                const uint32_t* pbl = &bl[ni >> 1][(ni & 1) * 2];
                mma_fp16(c[mi][ni], ah[mi], pbh);
                mma_fp16(c[mi][ni], ah[mi], pbl);
            }
    }

    // epilogue: c0=(r,2c), c1=(r,2c+1), c2=(r+8,2c), c3=(r+8,2c+1)
#pragma unroll
    for (int mi = 0; mi < 2; mi++) {
#pragma unroll
        for (int ni = 0; ni < 4; ni++) {
            int gr = row0 + wm * 32 + mi * 16 + l28;
            int gc = wn * 32 + ni * 8 + 2 * l4;
            float b0 = bias[gc], b1 = bias[gc + 1];
            if (gr < M) {
                float ox = c[mi][ni][0] + b0;
                float oy = c[mi][ni][1] + b1;
                if (MODE == 2) {
                    float2 r = *(const float2*)(R + (size_t)gr * 128 + gc);
                    ox += r.x; oy += r.y;
                }
                if (MODE == 1) {
                    ((__half2*)Cout)[(size_t)gr * 64 + (gc >> 1)] = __floats2half2_rn(ox, oy);
                } else {
                    *(float2*)((float*)Cout + (size_t)gr * 128 + gc) = make_float2(ox, oy);
                }
            }
            if (gr + 8 < M) {
                float ox = c[mi][ni][2] + b0;
                float oy = c[mi][ni][3] + b1;
                if (MODE == 2) {
                    float2 r = *(const float2*)(R + (size_t)(gr + 8) * 128 + gc);
                    ox += r.x; oy += r.y;
                }
                if (MODE == 1) {
                    ((__half2*)Cout)[(size_t)(gr + 8) * 64 + (gc >> 1)] = __floats2half2_rn(ox, oy);
                } else {
                    *(float2*)((float*)Cout + (size_t)(gr + 8) * 128 + gc) = make_float2(ox, oy);
                }
            }
        }
    }
}

// ---------------- fused per-node attention (one warp per node, 4-edge unroll, fp16 K/V) ----------------
__device__ __forceinline__ float dot_kh(const float4& q, uint2 u) {
    float2 a = __half22float2(*(__half2*)&u.x);
    float2 b = __half22float2(*(__half2*)&u.y);
    return q.x * a.x + q.y * a.y + q.z * b.x + q.w * b.y;
}

__global__ __launch_bounds__(256) void k_attn(int NN) {
    int warp = threadIdx.x >> 5;
    int lane = threadIdx.x & 31;
    int n = blockIdx.x * 8 + warp;
    if (n >= NN) return;

    const float4* Q4 = (const float4*)g_Q;
    const uint2* K2 = (const uint2*)g_Kh;   // row = 32 uint2 (128 halves)
    const uint2* V2 = (const uint2*)g_Vh;

    float4 q = Q4[(size_t)n * 32 + lane];   // lane holds dims [lane*4, lane*4+4); head = lane/8
    float z = 0.0f;
    float ax = 0.0f, ay = 0.0f, az = 0.0f, aw = 0.0f;
    const float sc = 0.17677669529663687f;  // 1/sqrt(32)

    int beg = g_offset[n];
    int end = g_offset[n + 1];
    int j = beg;
    for (; j + 4 <= end; j += 4) {
        int d0 = g_edge_dst[j + 0];
        int d1 = g_edge_dst[j + 1];
        int d2 = g_edge_dst[j + 2];
        int d3 = g_edge_dst[j + 3];
        uint2 k0 = K2[(size_t)d0 * 32 + lane];
        uint2 k1 = K2[(size_t)d1 * 32 + lane];
        uint2 k2 = K2[(size_t)d2 * 32 + lane];
        uint2 k3 = K2[(size_t)d3 * 32 + lane];
        uint2 v0 = V2[(size_t)d0 * 32 + lane];
        uint2 v1 = V2[(size_t)d1 * 32 + lane];
        uint2 v2 = V2[(size_t)d2 * 32 + lane];
        uint2 v3 = V2[(size_t)d3 * 32 + lane];

        float p0 = dot_kh(q, k0);
        float p1 = dot_kh(q, k1);
        float p2 = dot_kh(q, k2);
        float p3 = dot_kh(q, k3);
#pragma unroll
        for (int o = 1; o <= 4; o <<= 1) {
            p0 += __shfl_xor_sync(0xffffffffu, p0, o);
            p1 += __shfl_xor_sync(0xffffffffu, p1, o);
            p2 += __shfl_xor_sync(0xffffffffu, p2, o);
            p3 += __shfl_xor_sync(0xffffffffu, p3, o);
        }
        float e0 = __expf(p0 * sc);
        float e1 = __expf(p1 * sc);
        float e2 = __expf(p2 * sc);
        float e3 = __expf(p3 * sc);
        z += (e0 + e1) + (e2 + e3);
        float2 va, vb;
        va = __half22float2(*(__half2*)&v0.x); vb = __half22float2(*(__half2*)&v0.y);
        ax += e0 * va.x; ay += e0 * va.y; az += e0 * vb.x; aw += e0 * vb.y;
        va = __half22float2(*(__half2*)&v1.x); vb = __half22float2(*(__half2*)&v1.y);
        ax += e1 * va.x; ay += e1 * va.y; az += e1 * vb.x; aw += e1 * vb.y;
        va = __half22float2(*(__half2*)&v2.x); vb = __half22float2(*(__half2*)&v2.y);
        ax += e2 * va.x; ay += e2 * va.y; az += e2 * vb.x; aw += e2 * vb.y;
        va = __half22float2(*(__half2*)&v3.x); vb = __half22float2(*(__half2*)&v3.y);
        ax += e3 * va.x; ay += e3 * va.y; az += e3 * vb.x; aw += e3 * vb.y;
    }
    for (; j < end; j++) {
        int d = g_edge_dst[j];
        uint2 ku = K2[(size_t)d * 32 + lane];
        uint2 vu = V2[(size_t)d * 32 + lane];
        float p = dot_kh(q, ku);
        p += __shfl_xor_sync(0xffffffffu, p, 1);
        p += __shfl_xor_sync(0xffffffffu, p, 2);
        p += __shfl_xor_sync(0xffffffffu, p, 4);
        float e = __expf(p * sc);
        z += e;
        float2 va = __half22float2(*(__half2*)&vu.x);
        float2 vb = __half22float2(*(__half2*)&vu.y);
        ax += e * va.x; ay += e * va.y; az += e * vb.x; aw += e * vb.y;
    }
    float inv = (z > 0.0f) ? (1.0f / z) : 0.0f;
    float4 o;
    o.x = ax * inv; o.y = ay * inv; o.z = az * inv; o.w = aw * inv;
    ((float4*)g_attn)[(size_t)n * 32 + lane] = o;
}

// ---------------- launch ----------------
extern "C" void kernel_launch(void* const* d_in, const int* in_sizes, int n_in,
                              void* d_out, int out_size)
{
    const float* x_node = (const float*)d_in[0];
    const float* x_edge = (const float*)d_in[1];
    const int*   src    = (const int*)d_in[2];
    const int*   dst    = (const int*)d_in[3];
    const float* Wq     = (const float*)d_in[4];
    const float* bq     = (const float*)d_in[5];
    const float* Wk     = (const float*)d_in[6];
    const float* bk     = (const float*)d_in[7];
    const float* Wv     = (const float*)d_in[8];
    const float* bv     = (const float*)d_in[9];
    const float* Wo     = (const float*)d_in[10];
    const float* bo     = (const float*)d_in[11];
    float* out = (float*)d_out;

    int NN = in_sizes[0] / 128;
    int ME = in_sizes[1] / 128;
    int E  = in_sizes[2];

    float *Qp, *Ap;
    __half *Khp, *Vhp;
    uint4* Wspp;
    cudaGetSymbolAddress((void**)&Qp, g_Q);
    cudaGetSymbolAddress((void**)&Khp, g_Kh);
    cudaGetSymbolAddress((void**)&Vhp, g_Vh);
    cudaGetSymbolAddress((void**)&Ap, g_attn);
    cudaGetSymbolAddress((void**)&Wspp, g_Wsp);
    const size_t wstride = (size_t)2 * 128 * 136 * sizeof(__half) / sizeof(uint4);

    cudaFuncSetAttribute(k_gemmB<0>, cudaFuncAttributeMaxDynamicSharedMemorySize, GEMM_SMEM);
    cudaFuncSetAttribute(k_gemmB<1>, cudaFuncAttributeMaxDynamicSharedMemorySize, GEMM_SMEM);
    cudaFuncSetAttribute(k_gemmB<2>, cudaFuncAttributeMaxDynamicSharedMemorySize, GEMM_SMEM);

    k_zero<<<(NN + 255) / 256, 256>>>(NN);
    k_splitW<<<dim3(64, 4), 256>>>(Wq, Wk, Wv, Wo);
    k_gemmB<0><<<(NN + 63) / 64, 256, GEMM_SMEM>>>(x_node, Wspp + 0 * wstride, bq, nullptr, Qp, NN);
    k_gemmB<1><<<(ME + 63) / 64, 256, GEMM_SMEM>>>(x_edge, Wspp + 1 * wstride, bk, nullptr, Khp, ME);
    k_gemmB<1><<<(ME + 63) / 64, 256, GEMM_SMEM>>>(x_edge, Wspp + 2 * wstride, bv, nullptr, Vhp, ME);
    k_hist<<<(E + 255) / 256, 256>>>(src, E);
    k_scan<<<1, 1024>>>(NN);
    k_scatter<<<(E + 255) / 256, 256>>>(src, dst, E);
    k_attn<<<(NN + 7) / 8, 256>>>(NN);
    k_gemmB<2><<<(NN + 63) / 64, 256, GEMM_SMEM>>>(Ap, Wspp + 3 * wstride, bo, x_node, out, NN);
}